// round 10
// baseline (speedup 1.0000x reference)
#include <cuda_runtime.h>
#include <stdint.h>

typedef unsigned long long ull;

// ---------- f32x2 packed-fp32 helpers ----------
__device__ __forceinline__ ull pk2(float lo, float hi) {
    ull r; asm("mov.b64 %0,{%1,%2};" : "=l"(r) : "f"(lo), "f"(hi)); return r;
}
__device__ __forceinline__ void upk2(ull v, float& lo, float& hi) {
    asm("mov.b64 {%0,%1},%2;" : "=f"(lo), "=f"(hi) : "l"(v));
}
__device__ __forceinline__ ull ffma2(ull a, ull b, ull c) {
    ull d; asm("fma.rn.f32x2 %0,%1,%2,%3;" : "=l"(d) : "l"(a), "l"(b), "l"(c)); return d;
}
__device__ __forceinline__ ull fadd2(ull a, ull b) {
    ull d; asm("add.rn.f32x2 %0,%1,%2;" : "=l"(d) : "l"(a), "l"(b)); return d;
}

// ---------- L2 sync primitives ----------
__device__ __forceinline__ ull ld_rlx(const ull* p) {
    ull v;
    asm volatile("ld.relaxed.gpu.global.u64 %0, [%1];" : "=l"(v) : "l"(p) : "memory");
    return v;
}
__device__ __forceinline__ void st_rlx(ull* p, ull v) {
    asm volatile("st.relaxed.gpu.global.u64 [%0], %1;" :: "l"(p), "l"(v) : "memory");
}
__device__ __forceinline__ unsigned ld_acq_u32(const unsigned* p) {
    unsigned v;
    asm volatile("ld.acquire.gpu.global.u32 %0, [%1];" : "=r"(v) : "l"(p) : "memory");
    return v;
}
__device__ __forceinline__ void st_rel_u32(unsigned* p, unsigned v) {
    asm volatile("st.release.gpu.global.u32 [%0], %1;" :: "l"(p), "r"(v) : "memory");
}

// ---------- problem constants ----------
#define BATCH   64
#define SEQ     2048
#define FEAT    256
#define HID     256
#define G4      1024
#define BG      4
#define NGROUP  16
#define NWORK   128
#define NHELP   20
#define THREADS 512
#define CK      16      // k per chunk (16 chunks)

// ---------- scratch ----------
__device__ ull      ht_buf[NGROUP * 2 * BG * HID];      // tagged h [grp][par][b][k]
__device__ float    xp_part[(size_t)SEQ * BATCH * G4];  // helper partials [t][b][col]
__device__ unsigned flag_buf[SEQ];

// ============================================================
__global__ void init_kernel() {
    int t = blockIdx.x * blockDim.x + threadIdx.x;
    if (t < NGROUP * 1024) {
        int grp = t >> 10, rem = t & 1023;
        ht_buf[grp * 2048 + rem] = 0ull;    // parity-0: tag 0, h=0
    }
    if (t < SEQ) flag_buf[t] = 0u;
}

// ============================================================
// Helper: 20 CTAs (threads<256) precompute xp_part over
// offK = [64,128)  (worker warps 4..7, one per SMSP).
// ============================================================
__device__ void helper_body(int hj, const float* __restrict__ x,
                            const float* __restrict__ WX, char* smem)
{
    float (*xs)[68] = (float(*)[68])smem;
    float (*ws)[64] = (float(*)[64])(smem + 64 * 68 * 4);

    const int tid = threadIdx.x;
    const int ty = tid >> 4, tx = tid & 15;

    for (int t = hj; t < SEQ; t += NHELP) {
#pragma unroll
        for (int it = 0; it < 4; it++) {
            int f = tid + 256 * it;           // 0..1023
            int row = f >> 4, j = f & 15;
            float4 v = *(const float4*)&x[((size_t)row * SEQ + t) * FEAT + 64 + 4 * j];
            int kl = 4 * j;
            xs[kl + 0][row] = v.x; xs[kl + 1][row] = v.y;
            xs[kl + 2][row] = v.z; xs[kl + 3][row] = v.w;
        }
        for (int ct = 0; ct < 16; ct++) {
            __syncthreads();
#pragma unroll
            for (int it = 0; it < 4; it++) {
                int f2 = tid + 256 * it;
                int k = f2 >> 4, c4 = f2 & 15;
                float4 v = *(const float4*)&WX[(size_t)(64 + k) * G4 + 64 * ct + 4 * c4];
                *(float4*)&ws[k][4 * c4] = v;
            }
            __syncthreads();
            ull acc[4][2];
#pragma unroll
            for (int i = 0; i < 4; i++) { acc[i][0] = pk2(0.f, 0.f); acc[i][1] = pk2(0.f, 0.f); }
#pragma unroll 16
            for (int kk = 0; kk < 64; kk++) {
                float4 a4 = *(const float4*)&xs[kk][4 * ty];
                float4 b4 = *(const float4*)&ws[kk][4 * tx];
                ull b01 = pk2(b4.x, b4.y), b23 = pk2(b4.z, b4.w);
                ull am;
                am = pk2(a4.x, a4.x); acc[0][0] = ffma2(am, b01, acc[0][0]); acc[0][1] = ffma2(am, b23, acc[0][1]);
                am = pk2(a4.y, a4.y); acc[1][0] = ffma2(am, b01, acc[1][0]); acc[1][1] = ffma2(am, b23, acc[1][1]);
                am = pk2(a4.z, a4.z); acc[2][0] = ffma2(am, b01, acc[2][0]); acc[2][1] = ffma2(am, b23, acc[2][1]);
                am = pk2(a4.w, a4.w); acc[3][0] = ffma2(am, b01, acc[3][0]); acc[3][1] = ffma2(am, b23, acc[3][1]);
            }
            size_t base = ((size_t)t * BATCH + 4 * ty) * G4 + 64 * ct + 4 * tx;
#pragma unroll
            for (int i = 0; i < 4; i++) {
                float4 o;
                upk2(acc[i][0], o.x, o.y);
                upk2(acc[i][1], o.z, o.w);
                *(float4*)&xp_part[base + (size_t)i * G4] = o;
            }
        }
        __syncthreads();
        if (tid == 0) st_rel_u32(&flag_buf[t], 1u);
        __syncthreads();
    }
}

// ============================================================
// Worker: 128 CTAs x 512 threads (16 warps, 4/SMSP).
// Warp w owns K-chunk [16w,16w+16): WH slice in 64 regs/thread,
// polls its own producer slots (2/lane), hd/xd warp-private.
// Warps 4-7 skip xp (helpers cover k in [64,128) — one per SMSP).
// ============================================================
__device__ __forceinline__ float fsig(float x) {
    return __fdividef(1.0f, 1.0f + __expf(-x));
}
__device__ __forceinline__ float ftanh(float x) { return 2.0f * fsig(2.0f * x) - 1.0f; }

__device__ void worker_body(float* __restrict__ out,
                            const float* __restrict__ x,
                            const float* __restrict__ WX,
                            const float* __restrict__ WH,
                            const float* __restrict__ BX,
                            const float* __restrict__ BH,
                            long long out_size, char* smem)
{
    ulonglong2* wx_u2   = (ulonglong2*)smem;                      // [256][32]  128 KB
    ull*        hd      = (ull*)(smem + 131072);                  // [256][4]     8 KB
    ull*        xd      = (ull*)(smem + 131072 + 8192);           // [256][4]     8 KB
    ulonglong2* red     = (ulonglong2*)(smem + 131072 + 16384);   // [2][4][16][32] 64 KB
    float*      gates_s = (float*)(smem + 131072 + 16384 + 65536);// [4][128]     2 KB

    const int tid = threadIdx.x;
    const int grp = blockIdx.x >> 3;
    const int r   = blockIdx.x & 7;
    const int batch0 = grp * BG;

    const int w    = tid >> 5;           // chunk 0..15
    const int lane = tid & 31;
    const int cq   = lane;
    const int kbase = CK * w;
    const int kown  = kbase + (lane & 15);
    const int bb    = (lane >> 4) << 1;  // batch pair base: 0 or 2
    const bool xact = (w < 4) | (w > 7); // warps 4-7 offloaded (one per SMSP)
    const int rb = tid >> 5;             // act batch (tid<128)
    const int rc = lane;

    // ---- WX slice into SMEM, pre-packed ----
    for (int idx = tid; idx < 8192; idx += THREADS) {
        int f = idx >> 5, ci = idx & 31;
        int gcl = (ci >> 3) * HID + 32 * r + ((4 * ci) & 31);
        float4 w4 = *(const float4*)&WX[(size_t)f * G4 + gcl];
        wx_u2[idx] = make_ulonglong2(pk2(w4.x, w4.y), pk2(w4.z, w4.w));
    }

    // ---- WH chunk into registers (64 regs) ----
    ull wA[CK], wB[CK];
    {
        const int gc = (cq >> 3) * HID + 32 * r + ((4 * cq) & 31);
        const float* wp = WH + (size_t)kbase * G4 + gc;
#pragma unroll
        for (int kk = 0; kk < CK; kk++) {
            float4 w4 = *(const float4*)(wp + (size_t)kk * G4);
            wA[kk] = pk2(w4.x, w4.y);
            wB[kk] = pk2(w4.z, w4.w);
        }
    }

    // ---- bias + gate-col for act threads ----
    ull biasA = pk2(0.f, 0.f), biasB = biasA;
    int gcol = 0;
    if (tid < 128) {
        gcol = (rc >> 3) * HID + 32 * r + ((4 * rc) & 31);
        float4 bx4 = *(const float4*)&BX[gcol];
        float4 bh4 = *(const float4*)&BH[gcol];
        biasA = pk2(bx4.x + bh4.x, bx4.y + bh4.y);
        biasB = pk2(bx4.z + bh4.z, bx4.w + bh4.w);
    }

    // ---- x: this thread feeds (kown, bb) and (kown, bb+1) ----
    const float* xb0 = x + ((size_t)(batch0 + bb) * SEQ) * FEAT + kown;
    const float* xb1 = xb0 + (size_t)SEQ * FEAT;
    float xr0 = 0.f, xr1 = 0.f;
    if (xact) {
        float a0 = xb0[0], a1 = xb1[0];          // x(0)
        xd[kown * BG + bb]     = pk2(a0, a0);
        xd[kown * BG + bb + 1] = pk2(a1, a1);
        xr0 = xb0[FEAT];                          // x(1)
        xr1 = xb1[FEAT];
    }
    __syncthreads();

    ull* htg = &ht_buf[(size_t)grp * 2048];       // [par][b][k]

    ull a00, a01, a10, a11, a20, a21, a30, a31;
    a00 = a01 = a10 = a11 = a20 = a21 = a30 = a31 = pk2(0.f, 0.f);
    if (xact) {   // prologue xp-GEMM(0)
        const ull* xp_ = xd + kbase * BG;
        const ulonglong2* wp = wx_u2 + kbase * 32 + cq;
#pragma unroll
        for (int kk = 0; kk < CK; kk++) {
            ulonglong2 d0 = *(const ulonglong2*)(xp_ + kk * 4);
            ulonglong2 d1 = *(const ulonglong2*)(xp_ + kk * 4 + 2);
            ulonglong2 w2 = wp[kk * 32];
            a00 = ffma2(d0.x, w2.x, a00); a01 = ffma2(d0.x, w2.y, a01);
            a10 = ffma2(d0.y, w2.x, a10); a11 = ffma2(d0.y, w2.y, a11);
            a20 = ffma2(d1.x, w2.x, a20); a21 = ffma2(d1.x, w2.y, a21);
            a30 = ffma2(d1.y, w2.x, a30); a31 = ffma2(d1.y, w2.y, a31);
        }
    }

    // ---- speculative preload t=0 (parity-0 zeroed: guaranteed hit) ----
    ull sv0 = ld_rlx(htg + bb * 256 + kown);
    ull sv1 = ld_rlx(htg + (bb + 1) * 256 + kown);

    float cstate = 0.0f, hlast = 0.0f;

    for (int t = 0; t < SEQ; t++) {
        const int par = t & 1;

        // ---- stage x(t+1) (warp-private xd) ----
        if (xact) {
            xd[kown * BG + bb]     = pk2(xr0, xr0);
            xd[kown * BG + bb + 1] = pk2(xr1, xr1);
        }

        // ---- poll own slots; pack hd (warp-private) ----
        {
            const ull* sp0 = htg + (size_t)par * 1024 + bb * 256 + kown;
            const unsigned tg = (unsigned)t;
            while (((unsigned)(sv0 >> 32) != tg) | ((unsigned)(sv1 >> 32) != tg)) {
                sv0 = ld_rlx(sp0); sv1 = ld_rlx(sp0 + 256);
            }
            float h0 = __uint_as_float((unsigned)sv0);
            float h1 = __uint_as_float((unsigned)sv1);
            hd[kown * BG + bb]     = pk2(h0, h0);
            hd[kown * BG + bb + 1] = pk2(h1, h1);
        }
        __syncwarp();

        // ---- flag-gated xp_part prefetch (act threads; hides under h-GEMM) ----
        float4 xpp = make_float4(0.f, 0.f, 0.f, 0.f);
        if (tid < 128) {
            while (ld_acq_u32(&flag_buf[t]) == 0u) { }
            xpp = __ldcg((const float4*)&xp_part[((size_t)t * BATCH + batch0 + rb) * G4 + gcol]);
        }

        // ---- h-GEMM chunk (accumulates onto xp-partials) ----
        {
            const ull* hp = hd + kbase * BG;
#pragma unroll
            for (int kk = 0; kk < CK; kk++) {
                ulonglong2 d0 = *(const ulonglong2*)(hp + kk * 4);
                ulonglong2 d1 = *(const ulonglong2*)(hp + kk * 4 + 2);
                a00 = ffma2(d0.x, wA[kk], a00); a01 = ffma2(d0.x, wB[kk], a01);
                a10 = ffma2(d0.y, wA[kk], a10); a11 = ffma2(d0.y, wB[kk], a11);
                a20 = ffma2(d1.x, wA[kk], a20); a21 = ffma2(d1.x, wB[kk], a21);
                a30 = ffma2(d1.y, wA[kk], a30); a31 = ffma2(d1.y, wB[kk], a31);
            }
        }
        {   // stage: red[par][b][w][cq]
            ulonglong2* rp = red + (size_t)par * 2048;
            rp[(0 * 16 + w) * 32 + cq] = make_ulonglong2(a00, a01);
            rp[(1 * 16 + w) * 32 + cq] = make_ulonglong2(a10, a11);
            rp[(2 * 16 + w) * 32 + cq] = make_ulonglong2(a20, a21);
            rp[(3 * 16 + w) * 32 + cq] = make_ulonglong2(a30, a31);
        }
        __syncthreads();   // the ONE CTA-wide sync per step

        // ---- reduce 16 partials (+bias +xp_part) -> act -> publish ----
        if (tid < 128) {
            const ulonglong2* q = red + (size_t)par * 2048 + rb * 512;
            ull s0 = fadd2(biasA, pk2(xpp.x, xpp.y));
            ull s1 = fadd2(biasB, pk2(xpp.z, xpp.w));
#pragma unroll
            for (int j = 0; j < 16; j++) {
                ulonglong2 v = q[j * 32 + rc];
                s0 = fadd2(s0, v.x);
                s1 = fadd2(s1, v.y);
            }
            float g0, g1, g2, g3;
            upk2(s0, g0, g1); upk2(s1, g2, g3);
            *(float4*)&gates_s[rb * 128 + 4 * rc] = make_float4(g0, g1, g2, g3);
        }
        __syncwarp();
        if (tid < 128) {
            float gi = gates_s[rb * 128 +       rc];
            float gf = gates_s[rb * 128 +  32 + rc];
            float gg = gates_s[rb * 128 +  64 + rc];
            float go = gates_s[rb * 128 +  96 + rc];
            float i_ = fsig(gi), f_ = fsig(gf), g_ = ftanh(gg), o_ = fsig(go);
            cstate = f_ * cstate + i_ * g_;
            float h_ = o_ * ftanh(cstate);
            hlast = h_;
            const int kidx = 32 * r + rc;
            ull pv = (ull)__float_as_uint(h_) | ((ull)(unsigned)(t + 1) << 32);
            st_rlx(htg + (size_t)(par ^ 1) * 1024 + rb * 256 + kidx, pv);
            out[((size_t)(batch0 + rb) * SEQ + t) * HID + kidx] = h_;
        }

        // ---- prefetch x(t+2) ----
        if (xact) {
            size_t tn = (size_t)((t + 2 < SEQ) ? (t + 2) : t) * FEAT;
            xr0 = xb0[tn];
            xr1 = xb1[tn];
        }

        // ---- xp-GEMM(t+1) with mid-point speculative polls ----
        a00 = a01 = a10 = a11 = a20 = a21 = a30 = a31 = pk2(0.f, 0.f);
        if (xact) {
            const ull* xp_ = xd + kbase * BG;
            const ulonglong2* wp = wx_u2 + kbase * 32 + cq;
#pragma unroll
            for (int kk = 0; kk < 8; kk++) {
                ulonglong2 d0 = *(const ulonglong2*)(xp_ + kk * 4);
                ulonglong2 d1 = *(const ulonglong2*)(xp_ + kk * 4 + 2);
                ulonglong2 w2 = wp[kk * 32];
                a00 = ffma2(d0.x, w2.x, a00); a01 = ffma2(d0.x, w2.y, a01);
                a10 = ffma2(d0.y, w2.x, a10); a11 = ffma2(d0.y, w2.y, a11);
                a20 = ffma2(d1.x, w2.x, a20); a21 = ffma2(d1.x, w2.y, a21);
                a30 = ffma2(d1.y, w2.x, a30); a31 = ffma2(d1.y, w2.y, a31);
            }
            {   // speculative polls for t+1
                const ull* sp = htg + (size_t)(par ^ 1) * 1024 + bb * 256 + kown;
                sv0 = ld_rlx(sp); sv1 = ld_rlx(sp + 256);
            }
#pragma unroll
            for (int kk = 8; kk < CK; kk++) {
                ulonglong2 d0 = *(const ulonglong2*)(xp_ + kk * 4);
                ulonglong2 d1 = *(const ulonglong2*)(xp_ + kk * 4 + 2);
                ulonglong2 w2 = wp[kk * 32];
                a00 = ffma2(d0.x, w2.x, a00); a01 = ffma2(d0.x, w2.y, a01);
                a10 = ffma2(d0.y, w2.x, a10); a11 = ffma2(d0.y, w2.y, a11);
                a20 = ffma2(d1.x, w2.x, a20); a21 = ffma2(d1.x, w2.y, a21);
                a30 = ffma2(d1.y, w2.x, a30); a31 = ffma2(d1.y, w2.y, a31);
            }
        } else {
            const ull* sp = htg + (size_t)(par ^ 1) * 1024 + bb * 256 + kown;
            sv0 = ld_rlx(sp); sv1 = ld_rlx(sp + 256);
        }
    }

    if (tid < 128 && out_size >= (long long)BATCH * SEQ * HID + BATCH * HID) {
        out[(size_t)BATCH * SEQ * HID + (size_t)(batch0 + rb) * HID + 32 * r + rc] = hlast;
    }
}

// ============================================================
__global__ __launch_bounds__(THREADS, 1)
void lstm_kernel(float* __restrict__ out,
                 const float* __restrict__ x,
                 const float* __restrict__ WX,
                 const float* __restrict__ WH,
                 const float* __restrict__ BX,
                 const float* __restrict__ BH,
                 long long out_size)
{
    extern __shared__ char smem[];
    if (blockIdx.x >= NWORK) {
        if (threadIdx.x < 256) helper_body(blockIdx.x - NWORK, x, WX, smem);
    } else {
        worker_body(out, x, WX, WH, BX, BH, out_size, smem);
    }
}

// ============================================================
extern "C" void kernel_launch(void* const* d_in, const int* in_sizes, int n_in,
                              void* d_out, int out_size)
{
    const float* x  = (const float*)d_in[0];
    const float* WX = (const float*)d_in[1];
    const float* WH = (const float*)d_in[2];
    const float* BX = (const float*)d_in[3];
    const float* BH = (const float*)d_in[4];
    float* out = (float*)d_out;

    const size_t smem_bytes = 131072 + 8192 + 8192 + 65536 + 2048;  // 215040
    cudaFuncSetAttribute(lstm_kernel, cudaFuncAttributeMaxDynamicSharedMemorySize,
                         (int)smem_bytes);

    init_kernel<<<64, 256>>>();
    lstm_kernel<<<NWORK + NHELP, THREADS, smem_bytes>>>(
        out, x, WX, WH, BX, BH, (long long)out_size);
}